// round 9
// baseline (speedup 1.0000x reference)
#include <cuda_runtime.h>

// InterpolateSparse2d: bilinear sampling of x[B,C,Hx,Wx] at pos[B,N,2] -> out[B,N,C]
// Software-pipelined chunked two-phase:
//   launch 0:      transpose chunk 0
//   launch k=1..7: FUSED [gather chunk k-1 | transpose chunk k]  (independent roles)
//   launch 8:      gather chunk 7
// Double-buffered 2x39.3MB NHWC scratch stays L2-resident; x read with __ldcs,
// out written with __stcs so the streams don't evict the scratch.
#define BX 16
#define CX 64
#define HXX 240
#define WXX 320
#define NP 20000
#define HW (HXX * WXX)       // 76800
#define CHUNK_B 2
#define NCHUNK (BX / CHUNK_B)          // 8
#define CHUNK_ELEMS ((size_t)CHUNK_B * HW * CX)

#define N_T_BLOCKS ((HW / 32) * (CX / 32) * CHUNK_B)   // 2400*2*2 = 9600
#define N_G_BLOCKS ((CHUNK_B * NP + 15) / 16)          // 2500
#define N_BOTH_BLOCKS 12500   // ceil over 5-periodic interleave: 4 T : 1 G

// Double-buffered NHWC scratch: [2][CHUNK_B, Hx, Wx, C] = 78.6 MB total
__device__ float g_nhwc[2][CHUNK_ELEMS];

// ---------------------------------------------------------------------------
__device__ __forceinline__ void transpose_body(
    int wid, int t_chunk, const float* __restrict__ x, float tile[32][33])
{
    const int tx = threadIdx.x & 31;
    const int ty = threadIdx.x >> 5;          // 0..7

    const int b  = wid / (2400 * (CX / 32)); // batch within chunk
    const int r  = wid % (2400 * (CX / 32));
    const int c0 = (r / 2400) * 32;
    const int s0 = (r % 2400) * 32;

    const float* src = x + (size_t)t_chunk * CHUNK_ELEMS
                         + ((size_t)b * CX + c0) * HW + s0;
    #pragma unroll
    for (int i = 0; i < 32; i += 8)
        tile[ty + i][tx] = __ldcs(src + (size_t)(ty + i) * HW + tx);
    __syncthreads();

    float* dst = g_nhwc[t_chunk & 1] + ((size_t)b * HW + s0) * CX + c0;
    #pragma unroll
    for (int i = 0; i < 32; i += 8)
        dst[(size_t)(ty + i) * CX + tx] = tile[tx][ty + i];
}

// ---------------------------------------------------------------------------
__device__ __forceinline__ void gather_body(
    int wid, int g_chunk,
    const float* __restrict__ pos, const int* __restrict__ Hp,
    const int* __restrict__ Wp, float* __restrict__ out)
{
    const int c4 = threadIdx.x & 15;              // channel quad 0..15
    const int pl = wid * 16 + (threadIdx.x >> 4); // chunk-local point
    if (pl >= CHUNK_B * NP) return;

    const int p       = g_chunk * CHUNK_B * NP + pl;
    const int b_local = pl / NP;

    const float Wf = (float)__ldg(Wp);
    const float Hf = (float)__ldg(Hp);

    const float px = __ldg(pos + (size_t)p * 2 + 0);
    const float py = __ldg(pos + (size_t)p * 2 + 1);

    const float posx = px * (float)(WXX - 1) / Wf;
    const float posy = py * (float)(HXX - 1) / Hf;

    int x0 = (int)floorf(posx);
    x0 = min(max(x0, 0), WXX - 1);
    const int x1 = min(x0 + 1, WXX - 1);
    int y0 = (int)floorf(posy);
    y0 = min(max(y0, 0), HXX - 1);
    const int y1 = min(y0 + 1, HXX - 1);

    const float x0f = (float)x0, x1f = (float)x1;
    const float y0f = (float)y0, y1f = (float)y1;

    const float wa = (x1f - posx) * (y1f - posy);
    const float wb = (x1f - posx) * (posy - y0f);
    const float wc = (posx - x0f) * (y1f - posy);
    const float wd = (posx - x0f) * (posy - y0f);

    const float* buf = g_nhwc[g_chunk & 1];
    const size_t base = (size_t)b_local * HW;
    const float4* pa = (const float4*)(buf + (base + (size_t)y0 * WXX + x0) * CX);
    const float4* pb = (const float4*)(buf + (base + (size_t)y1 * WXX + x0) * CX);
    const float4* pc = (const float4*)(buf + (base + (size_t)y0 * WXX + x1) * CX);
    const float4* pd = (const float4*)(buf + (base + (size_t)y1 * WXX + x1) * CX);

    const float4 Ia = __ldg(pa + c4);
    const float4 Ib = __ldg(pb + c4);
    const float4 Ic = __ldg(pc + c4);
    const float4 Id = __ldg(pd + c4);

    float4 r;
    r.x = wa * Ia.x + wb * Ib.x + wc * Ic.x + wd * Id.x;
    r.y = wa * Ia.y + wb * Ib.y + wc * Ic.y + wd * Id.y;
    r.z = wa * Ia.z + wb * Ib.z + wc * Ic.z + wd * Id.z;
    r.w = wa * Ia.w + wb * Ib.w + wc * Ic.w + wd * Id.w;

    __stcs((float4*)(out + (size_t)p * CX) + c4, r);
}

// ---------------------------------------------------------------------------
// Fused pipeline stage: transpose chunk t_chunk (if >=0) and gather chunk
// g_chunk (if >=0) in one launch. Roles interleaved 4T:1G by blockIdx so both
// proceed concurrently across SMs. Roles touch different scratch buffers.
// ---------------------------------------------------------------------------
__global__ void __launch_bounds__(256) pipeline_stage_kernel(
    const float* __restrict__ x, const float* __restrict__ pos,
    const int* __restrict__ Hp, const int* __restrict__ Wp,
    float* __restrict__ out, int t_chunk, int g_chunk)
{
    __shared__ float tile[32][33];
    const int idx = blockIdx.x;

    if (t_chunk >= 0 && g_chunk >= 0) {
        const int grp = idx / 5;
        const int lane = idx % 5;
        if (lane == 4) {
            if (grp < N_G_BLOCKS) gather_body(grp, g_chunk, pos, Hp, Wp, out);
        } else {
            const int wid = grp * 4 + lane;
            if (wid < N_T_BLOCKS) transpose_body(wid, t_chunk, x, tile);
        }
    } else if (t_chunk >= 0) {
        transpose_body(idx, t_chunk, x, tile);
    } else {
        gather_body(idx, g_chunk, pos, Hp, Wp, out);
    }
}

extern "C" void kernel_launch(void* const* d_in, const int* in_sizes, int n_in,
                              void* d_out, int out_size) {
    const float* x   = (const float*)d_in[0];
    const float* pos = (const float*)d_in[1];
    const int*   Hp  = (const int*)d_in[2];
    const int*   Wp  = (const int*)d_in[3];
    float* out = (float*)d_out;

    // Prologue: fill buffer 0
    pipeline_stage_kernel<<<N_T_BLOCKS, 256>>>(x, pos, Hp, Wp, out, 0, -1);
    // Steady state: gather k-1 while transposing k
    for (int k = 1; k < NCHUNK; k++)
        pipeline_stage_kernel<<<N_BOTH_BLOCKS, 256>>>(x, pos, Hp, Wp, out, k, k - 1);
    // Epilogue: gather last chunk
    pipeline_stage_kernel<<<N_G_BLOCKS, 256>>>(x, pos, Hp, Wp, out, -1, NCHUNK - 1);
}